// round 9
// baseline (speedup 1.0000x reference)
#include <cuda_runtime.h>
#include <cuda_fp16.h>
#include <cstdint>

#define M_DIM 4096
#define K_DIM 4096
#define N_DIM 11008
#define NPACK (N_DIM / 8)   // 1376
#define GROUP 128

// Static scratch: W [K, N] fp16 (90.2 MB) + X [M, K] fp16 (32 MB).
__device__ __half g_W[(size_t)K_DIM * N_DIM];
__device__ __half g_X[(size_t)M_DIM * K_DIM];

// ---------------------------------------------------------------------------
// Fused prep: block.x < CONV_BLOCKS -> convert x f32->fp16; else AWQ dequant.
// ---------------------------------------------------------------------------
constexpr int CONV_BLOCKS = (M_DIM * K_DIM / 8) / 256;          // 8192
constexpr int DEQ_ELEMS   = K_DIM * NPACK;                      // 5,636,096
constexpr int DEQ_BLOCKS  = (DEQ_ELEMS + 255) / 256;            // 22016

__global__ void __launch_bounds__(256) prep_kernel(
    const float* __restrict__ x,
    const int* __restrict__ qweight,
    const int* __restrict__ qzeros,
    const float* __restrict__ scales)
{
    if (blockIdx.x < CONV_BLOCKS) {
        size_t i = ((size_t)blockIdx.x * 256 + threadIdx.x) * 8;
        float4 v0 = *reinterpret_cast<const float4*>(x + i);
        float4 v1 = *reinterpret_cast<const float4*>(x + i + 4);
        __half2 o[4];
        o[0] = __floats2half2_rn(v0.x, v0.y);
        o[1] = __floats2half2_rn(v0.z, v0.w);
        o[2] = __floats2half2_rn(v1.x, v1.y);
        o[3] = __floats2half2_rn(v1.z, v1.w);
        *reinterpret_cast<uint4*>(&g_X[i]) = *reinterpret_cast<const uint4*>(o);
        return;
    }
    int idx = (blockIdx.x - CONV_BLOCKS) * 256 + threadIdx.x;
    if (idx >= DEQ_ELEMS) return;
    int k = idx / NPACK;
    int c = idx - k * NPACK;
    int g = k >> 7;

    unsigned q = (unsigned)qweight[idx];
    unsigned z = (unsigned)qzeros[g * NPACK + c];

    float4 s0 = *reinterpret_cast<const float4*>(scales + (size_t)g * N_DIM + (size_t)c * 8);
    float4 s1 = *reinterpret_cast<const float4*>(scales + (size_t)g * N_DIM + (size_t)c * 8 + 4);
    float sf[8] = {s0.x, s0.y, s0.z, s0.w, s1.x, s1.y, s1.z, s1.w};

    const int shifts[8] = {0, 16, 4, 20, 8, 24, 12, 28};
    __half2 out[4];
#pragma unroll
    for (int j = 0; j < 4; ++j) {
        int i0 = (int)((q >> shifts[2 * j]) & 0xF) - (int)((z >> shifts[2 * j]) & 0xF);
        int i1 = (int)((q >> shifts[2 * j + 1]) & 0xF) - (int)((z >> shifts[2 * j + 1]) & 0xF);
        out[j] = __floats2half2_rn((float)i0 * sf[2 * j], (float)i1 * sf[2 * j + 1]);
    }
    *reinterpret_cast<uint4*>(&g_W[(size_t)k * N_DIM + (size_t)c * 8]) =
        *reinterpret_cast<const uint4*>(out);
}

// ---------------------------------------------------------------------------
// GEMM: CTA tile 128x128, BK=64, 3-stage cp.async, 4 warps (2x2),
// warp tile 64x64, register double-buffered fragments. 2 CTAs/SM.
// ---------------------------------------------------------------------------
constexpr int BM = 128, BN = 128, BK = 64;
constexpr int NK = K_DIM / BK;          // 64
constexpr int A_LD = BK + 8;            // 72 halves
constexpr int B_LD = BN + 8;            // 136 halves
constexpr int A_STAGE = BM * A_LD;      // 9216 halves
constexpr int B_STAGE = BK * B_LD;      // 8704 halves
constexpr int STAGE_H = A_STAGE + B_STAGE;       // 17920 halves
constexpr int NSTAGE = 3;
constexpr int GEMM_SMEM = NSTAGE * STAGE_H * 2;  // 107,520 B
constexpr int NTHREADS = 128;
constexpr int GROUP_M = 8;
constexpr int MT = M_DIM / BM;          // 32
constexpr int NT = N_DIM / BN;          // 86

extern __shared__ __half smem_h[];

__device__ __forceinline__ uint32_t smem_u32(const void* p) {
    uint32_t a;
    asm("{ .reg .u64 t; cvta.to.shared.u64 t, %1; cvt.u32.u64 %0, t; }"
        : "=r"(a) : "l"(p));
    return a;
}
__device__ __forceinline__ void cpa16(uint32_t s, const void* g) {
    asm volatile("cp.async.cg.shared.global [%0], [%1], 16;\n" :: "r"(s), "l"(g));
}
#define CP_COMMIT() asm volatile("cp.async.commit_group;\n" ::: "memory")
#define CP_WAIT(n)  asm volatile("cp.async.wait_group %0;\n" :: "n"(n) : "memory")

__device__ __forceinline__ void ldsm_x4(uint32_t& r0, uint32_t& r1, uint32_t& r2,
                                        uint32_t& r3, uint32_t addr) {
    asm volatile("ldmatrix.sync.aligned.m8n8.x4.shared.b16 {%0,%1,%2,%3}, [%4];"
                 : "=r"(r0), "=r"(r1), "=r"(r2), "=r"(r3) : "r"(addr));
}
__device__ __forceinline__ void ldsm_x4_t(uint32_t& r0, uint32_t& r1, uint32_t& r2,
                                          uint32_t& r3, uint32_t addr) {
    asm volatile("ldmatrix.sync.aligned.m8n8.x4.trans.shared.b16 {%0,%1,%2,%3}, [%4];"
                 : "=r"(r0), "=r"(r1), "=r"(r2), "=r"(r3) : "r"(addr));
}
__device__ __forceinline__ void mma16816(float* c, const uint32_t* a, const uint32_t* b) {
    asm volatile(
        "mma.sync.aligned.m16n8k16.row.col.f32.f16.f16.f32 "
        "{%0,%1,%2,%3}, {%4,%5,%6,%7}, {%8,%9}, {%0,%1,%2,%3};"
        : "+f"(c[0]), "+f"(c[1]), "+f"(c[2]), "+f"(c[3])
        : "r"(a[0]), "r"(a[1]), "r"(a[2]), "r"(a[3]), "r"(b[0]), "r"(b[1]));
}

// stage load (128 threads): A 1024 chunks + B 1024 chunks, 8 iters each.
__device__ __forceinline__ void load_stage(uint32_t sb, int tid, int m0, int n0, int kt)
{
    uint32_t a_s = sb;
    uint32_t b_s = sb + A_STAGE * 2;
#pragma unroll
    for (int i = 0; i < 8; ++i) {
        int cid = tid + NTHREADS * i;
        int row = cid >> 3;
        int kc  = cid & 7;
        cpa16(a_s + (row * A_LD + kc * 8) * 2,
              g_X + (size_t)(m0 + row) * K_DIM + kt + kc * 8);
    }
#pragma unroll
    for (int i = 0; i < 8; ++i) {
        int cid = tid + NTHREADS * i;
        int row = cid >> 4;
        int nc  = cid & 15;
        cpa16(b_s + (row * B_LD + nc * 8) * 2,
              g_W + (size_t)(kt + row) * N_DIM + n0 + nc * 8);
    }
}

// fragment load for one ks step into (AF, BF)
#define LOAD_FRAGS(ks, AF, BF) do {                                          \
    _Pragma("unroll")                                                        \
    for (int mf = 0; mf < 4; ++mf)                                           \
        ldsm_x4((AF)[mf][0], (AF)[mf][1], (AF)[mf][2], (AF)[mf][3],          \
                a_s + ((wm * 64 + mf * 16 + a_row) * A_LD + (ks) * 16 + a_c8) * 2); \
    _Pragma("unroll")                                                        \
    for (int nb = 0; nb < 4; ++nb)                                           \
        ldsm_x4_t((BF)[nb][0], (BF)[nb][1], (BF)[nb][2], (BF)[nb][3],        \
                  b_s + (((ks) * 16 + b_row) * B_LD + wn * 64 + nb * 16 + b_c8) * 2); \
} while (0)

__global__ void __launch_bounds__(NTHREADS, 2) gemm_kernel(
    const float* __restrict__ bias,
    float* __restrict__ out)
{
    const int tid  = threadIdx.x;
    const int warp = tid >> 5;
    const int lane = tid & 31;
    const int wm = warp >> 1;           // 0..1 -> 64-row slab
    const int wn = warp & 1;            // 0..1 -> 64-col slab

    int bid = blockIdx.x;
    int grp = bid / (GROUP_M * NT);
    int rem = bid - grp * (GROUP_M * NT);
    int mt  = grp * GROUP_M + rem % GROUP_M;
    int nt  = rem / GROUP_M;
    const int m0 = mt * BM;
    const int n0 = nt * BN;

    const uint32_t sb = smem_u32(smem_h);

    float c[4][8][4];
#pragma unroll
    for (int i = 0; i < 4; ++i)
#pragma unroll
        for (int j = 0; j < 8; ++j)
#pragma unroll
            for (int e = 0; e < 4; ++e) c[i][j][e] = 0.0f;

    // Prologue: stages 0, 1
#pragma unroll
    for (int s = 0; s < NSTAGE - 1; ++s) {
        load_stage(sb + s * STAGE_H * 2, tid, m0, n0, s * BK);
        CP_COMMIT();
    }

    const int a_row = lane & 15;
    const int a_c8  = (lane >> 4) * 8;
    const int b_row = lane & 15;
    const int b_c8  = (lane >> 4) * 8;

    for (int it = 0; it < NK; ++it) {
        CP_WAIT(1);            // stage `it` resident
        __syncthreads();

        int nxt = it + NSTAGE - 1;
        if (nxt < NK)
            load_stage(sb + (nxt % NSTAGE) * STAGE_H * 2, tid, m0, n0, nxt * BK);
        CP_COMMIT();

        const uint32_t a_s = sb + (it % NSTAGE) * STAGE_H * 2;
        const uint32_t b_s = a_s + A_STAGE * 2;

        // register double-buffered fragment pipeline over 4 ks steps
        uint32_t af[2][4][4], bf[2][4][4];
        LOAD_FRAGS(0, af[0], bf[0]);
#pragma unroll
        for (int ks = 0; ks < BK / 16; ++ks) {
            const int cur = ks & 1;
            if (ks < BK / 16 - 1)
                LOAD_FRAGS(ks + 1, af[cur ^ 1], bf[cur ^ 1]);
#pragma unroll
            for (int mf = 0; mf < 4; ++mf) {
#pragma unroll
                for (int nf = 0; nf < 8; ++nf) {
                    const uint32_t* bp = &bf[cur][nf >> 1][(nf & 1) * 2];
                    mma16816(c[mf][nf], af[cur][mf], bp);
                }
            }
        }
    }

    // -------- epilogue: fp16 round + fp16 bias, f32 stores ----------
    const int qr = lane >> 2;            // 0..7
    const int qc = (lane & 3) * 2;       // 0,2,4,6
#pragma unroll
    for (int nf = 0; nf < 8; ++nf) {
        int col = n0 + wn * 64 + nf * 8 + qc;
        float2 bv = *reinterpret_cast<const float2*>(bias + col);
        __half bh0 = __float2half(bv.x), bh1 = __float2half(bv.y);
#pragma unroll
        for (int mf = 0; mf < 4; ++mf) {
            int row = m0 + wm * 64 + mf * 16 + qr;
            float2 o0, o1;
            o0.x = __half2float(__hadd(__float2half(c[mf][nf][0]), bh0));
            o0.y = __half2float(__hadd(__float2half(c[mf][nf][1]), bh1));
            o1.x = __half2float(__hadd(__float2half(c[mf][nf][2]), bh0));
            o1.y = __half2float(__hadd(__float2half(c[mf][nf][3]), bh1));
            *reinterpret_cast<float2*>(&out[(size_t)row * N_DIM + col]) = o0;
            *reinterpret_cast<float2*>(&out[(size_t)(row + 8) * N_DIM + col]) = o1;
        }
    }
}

// ---------------------------------------------------------------------------
extern "C" void kernel_launch(void* const* d_in, const int* in_sizes, int n_in,
                              void* d_out, int out_size)
{
    const float* x      = (const float*)d_in[0];
    const int*   qw     = (const int*)d_in[1];
    const int*   qz     = (const int*)d_in[2];
    const float* scales = (const float*)d_in[3];
    const float* bias   = (const float*)d_in[4];
    float*       out    = (float*)d_out;

    cudaFuncSetAttribute(gemm_kernel, cudaFuncAttributeMaxDynamicSharedMemorySize,
                         GEMM_SMEM);

    prep_kernel<<<CONV_BLOCKS + DEQ_BLOCKS, 256>>>(x, qw, qz, scales);
    gemm_kernel<<<MT * NT, NTHREADS, GEMM_SMEM>>>(bias, out);
}

// round 10
// speedup vs baseline: 1.0009x; 1.0009x over previous
#include <cuda_runtime.h>
#include <cuda_fp16.h>
#include <cstdint>

#define M_DIM 4096
#define K_DIM 4096
#define N_DIM 11008
#define NPACK (N_DIM / 8)   // 1376
#define GROUP 128

// Static scratch: W [K, N] fp16 (90.2 MB) + X [M, K] fp16 (32 MB).
__device__ __half g_W[(size_t)K_DIM * N_DIM];
__device__ __half g_X[(size_t)M_DIM * K_DIM];

// ---------------------------------------------------------------------------
// Fused prep: block.x < CONV_BLOCKS -> convert x f32->fp16; else AWQ dequant.
// ---------------------------------------------------------------------------
constexpr int CONV_BLOCKS = (M_DIM * K_DIM / 8) / 256;          // 8192
constexpr int DEQ_ELEMS   = K_DIM * NPACK;                      // 5,636,096
constexpr int DEQ_BLOCKS  = (DEQ_ELEMS + 255) / 256;            // 22016

__global__ void __launch_bounds__(256) prep_kernel(
    const float* __restrict__ x,
    const int* __restrict__ qweight,
    const int* __restrict__ qzeros,
    const float* __restrict__ scales)
{
    if (blockIdx.x < CONV_BLOCKS) {
        size_t i = ((size_t)blockIdx.x * 256 + threadIdx.x) * 8;
        float4 v0 = *reinterpret_cast<const float4*>(x + i);
        float4 v1 = *reinterpret_cast<const float4*>(x + i + 4);
        __half2 o[4];
        o[0] = __floats2half2_rn(v0.x, v0.y);
        o[1] = __floats2half2_rn(v0.z, v0.w);
        o[2] = __floats2half2_rn(v1.x, v1.y);
        o[3] = __floats2half2_rn(v1.z, v1.w);
        *reinterpret_cast<uint4*>(&g_X[i]) = *reinterpret_cast<const uint4*>(o);
        return;
    }
    int idx = (blockIdx.x - CONV_BLOCKS) * 256 + threadIdx.x;
    if (idx >= DEQ_ELEMS) return;
    int k = idx / NPACK;
    int c = idx - k * NPACK;
    int g = k >> 7;

    unsigned q = (unsigned)qweight[idx];
    unsigned z = (unsigned)qzeros[g * NPACK + c];

    float4 s0 = *reinterpret_cast<const float4*>(scales + (size_t)g * N_DIM + (size_t)c * 8);
    float4 s1 = *reinterpret_cast<const float4*>(scales + (size_t)g * N_DIM + (size_t)c * 8 + 4);
    float sf[8] = {s0.x, s0.y, s0.z, s0.w, s1.x, s1.y, s1.z, s1.w};

    const int shifts[8] = {0, 16, 4, 20, 8, 24, 12, 28};
    __half2 out[4];
#pragma unroll
    for (int j = 0; j < 4; ++j) {
        int i0 = (int)((q >> shifts[2 * j]) & 0xF) - (int)((z >> shifts[2 * j]) & 0xF);
        int i1 = (int)((q >> shifts[2 * j + 1]) & 0xF) - (int)((z >> shifts[2 * j + 1]) & 0xF);
        out[j] = __floats2half2_rn((float)i0 * sf[2 * j], (float)i1 * sf[2 * j + 1]);
    }
    *reinterpret_cast<uint4*>(&g_W[(size_t)k * N_DIM + (size_t)c * 8]) =
        *reinterpret_cast<const uint4*>(out);
}

// ---------------------------------------------------------------------------
// GEMM: CTA tile 128x128, BK=64, 3-stage cp.async, 4 warps (2x2),
// warp tile 64x64, register double-buffered fragments. 2 CTAs/SM.
// ---------------------------------------------------------------------------
constexpr int BM = 128, BN = 128, BK = 64;
constexpr int NK = K_DIM / BK;          // 64
constexpr int A_LD = BK + 8;            // 72 halves
constexpr int B_LD = BN + 8;            // 136 halves
constexpr int A_STAGE = BM * A_LD;      // 9216 halves
constexpr int B_STAGE = BK * B_LD;      // 8704 halves
constexpr int STAGE_H = A_STAGE + B_STAGE;       // 17920 halves
constexpr int NSTAGE = 3;
constexpr int GEMM_SMEM = NSTAGE * STAGE_H * 2;  // 107,520 B
constexpr int NTHREADS = 128;
constexpr int GROUP_M = 8;
constexpr int MT = M_DIM / BM;          // 32
constexpr int NT = N_DIM / BN;          // 86

extern __shared__ __half smem_h[];

__device__ __forceinline__ uint32_t smem_u32(const void* p) {
    uint32_t a;
    asm("{ .reg .u64 t; cvta.to.shared.u64 t, %1; cvt.u32.u64 %0, t; }"
        : "=r"(a) : "l"(p));
    return a;
}
__device__ __forceinline__ void cpa16(uint32_t s, const void* g) {
    asm volatile("cp.async.cg.shared.global [%0], [%1], 16;\n" :: "r"(s), "l"(g));
}
#define CP_COMMIT() asm volatile("cp.async.commit_group;\n" ::: "memory")
#define CP_WAIT(n)  asm volatile("cp.async.wait_group %0;\n" :: "n"(n) : "memory")

__device__ __forceinline__ void ldsm_x4(uint32_t& r0, uint32_t& r1, uint32_t& r2,
                                        uint32_t& r3, uint32_t addr) {
    asm volatile("ldmatrix.sync.aligned.m8n8.x4.shared.b16 {%0,%1,%2,%3}, [%4];"
                 : "=r"(r0), "=r"(r1), "=r"(r2), "=r"(r3) : "r"(addr));
}
__device__ __forceinline__ void ldsm_x4_t(uint32_t& r0, uint32_t& r1, uint32_t& r2,
                                          uint32_t& r3, uint32_t addr) {
    asm volatile("ldmatrix.sync.aligned.m8n8.x4.trans.shared.b16 {%0,%1,%2,%3}, [%4];"
                 : "=r"(r0), "=r"(r1), "=r"(r2), "=r"(r3) : "r"(addr));
}
__device__ __forceinline__ void mma16816(float* c, const uint32_t* a, const uint32_t* b) {
    asm volatile(
        "mma.sync.aligned.m16n8k16.row.col.f32.f16.f16.f32 "
        "{%0,%1,%2,%3}, {%4,%5,%6,%7}, {%8,%9}, {%0,%1,%2,%3};"
        : "+f"(c[0]), "+f"(c[1]), "+f"(c[2]), "+f"(c[3])
        : "r"(a[0]), "r"(a[1]), "r"(a[2]), "r"(a[3]), "r"(b[0]), "r"(b[1]));
}

// stage load (128 threads): A 1024 chunks + B 1024 chunks, 8 iters each.
__device__ __forceinline__ void load_stage(uint32_t sb, int tid, int m0, int n0, int kt)
{
    uint32_t a_s = sb;
    uint32_t b_s = sb + A_STAGE * 2;
#pragma unroll
    for (int i = 0; i < 8; ++i) {
        int cid = tid + NTHREADS * i;
        int row = cid >> 3;
        int kc  = cid & 7;
        cpa16(a_s + (row * A_LD + kc * 8) * 2,
              g_X + (size_t)(m0 + row) * K_DIM + kt + kc * 8);
    }
#pragma unroll
    for (int i = 0; i < 8; ++i) {
        int cid = tid + NTHREADS * i;
        int row = cid >> 4;
        int nc  = cid & 15;
        cpa16(b_s + (row * B_LD + nc * 8) * 2,
              g_W + (size_t)(kt + row) * N_DIM + n0 + nc * 8);
    }
}

// fragment load for one ks step into (AF, BF)
#define LOAD_FRAGS(ks, AF, BF) do {                                          \
    _Pragma("unroll")                                                        \
    for (int mf = 0; mf < 4; ++mf)                                           \
        ldsm_x4((AF)[mf][0], (AF)[mf][1], (AF)[mf][2], (AF)[mf][3],          \
                a_s + ((wm * 64 + mf * 16 + a_row) * A_LD + (ks) * 16 + a_c8) * 2); \
    _Pragma("unroll")                                                        \
    for (int nb = 0; nb < 4; ++nb)                                           \
        ldsm_x4_t((BF)[nb][0], (BF)[nb][1], (BF)[nb][2], (BF)[nb][3],        \
                  b_s + (((ks) * 16 + b_row) * B_LD + wn * 64 + nb * 16 + b_c8) * 2); \
} while (0)

__global__ void __launch_bounds__(NTHREADS, 2) gemm_kernel(
    const float* __restrict__ bias,
    float* __restrict__ out)
{
    const int tid  = threadIdx.x;
    const int warp = tid >> 5;
    const int lane = tid & 31;
    const int wm = warp >> 1;           // 0..1 -> 64-row slab
    const int wn = warp & 1;            // 0..1 -> 64-col slab

    int bid = blockIdx.x;
    int grp = bid / (GROUP_M * NT);
    int rem = bid - grp * (GROUP_M * NT);
    int mt  = grp * GROUP_M + rem % GROUP_M;
    int nt  = rem / GROUP_M;
    const int m0 = mt * BM;
    const int n0 = nt * BN;

    const uint32_t sb = smem_u32(smem_h);

    float c[4][8][4];
#pragma unroll
    for (int i = 0; i < 4; ++i)
#pragma unroll
        for (int j = 0; j < 8; ++j)
#pragma unroll
            for (int e = 0; e < 4; ++e) c[i][j][e] = 0.0f;

    // Prologue: stages 0, 1
#pragma unroll
    for (int s = 0; s < NSTAGE - 1; ++s) {
        load_stage(sb + s * STAGE_H * 2, tid, m0, n0, s * BK);
        CP_COMMIT();
    }

    const int a_row = lane & 15;
    const int a_c8  = (lane >> 4) * 8;
    const int b_row = lane & 15;
    const int b_c8  = (lane >> 4) * 8;

    for (int it = 0; it < NK; ++it) {
        CP_WAIT(1);            // stage `it` resident
        __syncthreads();

        int nxt = it + NSTAGE - 1;
        if (nxt < NK)
            load_stage(sb + (nxt % NSTAGE) * STAGE_H * 2, tid, m0, n0, nxt * BK);
        CP_COMMIT();

        const uint32_t a_s = sb + (it % NSTAGE) * STAGE_H * 2;
        const uint32_t b_s = a_s + A_STAGE * 2;

        // register double-buffered fragment pipeline over 4 ks steps
        uint32_t af[2][4][4], bf[2][4][4];
        LOAD_FRAGS(0, af[0], bf[0]);
#pragma unroll
        for (int ks = 0; ks < BK / 16; ++ks) {
            const int cur = ks & 1;
            if (ks < BK / 16 - 1)
                LOAD_FRAGS(ks + 1, af[cur ^ 1], bf[cur ^ 1]);
#pragma unroll
            for (int mf = 0; mf < 4; ++mf) {
#pragma unroll
                for (int nf = 0; nf < 8; ++nf) {
                    const uint32_t* bp = &bf[cur][nf >> 1][(nf & 1) * 2];
                    mma16816(c[mf][nf], af[cur][mf], bp);
                }
            }
        }
    }

    // -------- epilogue: fp16 round + fp16 bias, f32 stores ----------
    const int qr = lane >> 2;            // 0..7
    const int qc = (lane & 3) * 2;       // 0,2,4,6
#pragma unroll
    for (int nf = 0; nf < 8; ++nf) {
        int col = n0 + wn * 64 + nf * 8 + qc;
        float2 bv = *reinterpret_cast<const float2*>(bias + col);
        __half bh0 = __float2half(bv.x), bh1 = __float2half(bv.y);
#pragma unroll
        for (int mf = 0; mf < 4; ++mf) {
            int row = m0 + wm * 64 + mf * 16 + qr;
            float2 o0, o1;
            o0.x = __half2float(__hadd(__float2half(c[mf][nf][0]), bh0));
            o0.y = __half2float(__hadd(__float2half(c[mf][nf][1]), bh1));
            o1.x = __half2float(__hadd(__float2half(c[mf][nf][2]), bh0));
            o1.y = __half2float(__hadd(__float2half(c[mf][nf][3]), bh1));
            *reinterpret_cast<float2*>(&out[(size_t)row * N_DIM + col]) = o0;
            *reinterpret_cast<float2*>(&out[(size_t)(row + 8) * N_DIM + col]) = o1;
        }
    }
}

// ---------------------------------------------------------------------------
extern "C" void kernel_launch(void* const* d_in, const int* in_sizes, int n_in,
                              void* d_out, int out_size)
{
    const float* x      = (const float*)d_in[0];
    const int*   qw     = (const int*)d_in[1];
    const int*   qz     = (const int*)d_in[2];
    const float* scales = (const float*)d_in[3];
    const float* bias   = (const float*)d_in[4];
    float*       out    = (float*)d_out;

    cudaFuncSetAttribute(gemm_kernel, cudaFuncAttributeMaxDynamicSharedMemorySize,
                         GEMM_SMEM);

    prep_kernel<<<CONV_BLOCKS + DEQ_BLOCKS, 256>>>(x, qw, qz, scales);
    gemm_kernel<<<MT * NT, NTHREADS, GEMM_SMEM>>>(bias, out);
}

// round 11
// speedup vs baseline: 1.0839x; 1.0829x over previous
#include <cuda_runtime.h>
#include <cuda_fp16.h>
#include <cstdint>

#define M_DIM 4096
#define K_DIM 4096
#define N_DIM 11008
#define NPACK (N_DIM / 8)   // 1376
#define GROUP 128

// Static scratch: W [K, N] fp16 (90.2 MB) + X [M, K] fp16 (32 MB).
__device__ __half g_W[(size_t)K_DIM * N_DIM];
__device__ __half g_X[(size_t)M_DIM * K_DIM];

// ---------------------------------------------------------------------------
// Fused prep: block.x < CONV_BLOCKS -> convert x f32->fp16; else AWQ dequant.
// ---------------------------------------------------------------------------
constexpr int CONV_BLOCKS = (M_DIM * K_DIM / 8) / 256;          // 8192
constexpr int DEQ_ELEMS   = K_DIM * NPACK;                      // 5,636,096
constexpr int DEQ_BLOCKS  = (DEQ_ELEMS + 255) / 256;            // 22016

__global__ void __launch_bounds__(256) prep_kernel(
    const float* __restrict__ x,
    const int* __restrict__ qweight,
    const int* __restrict__ qzeros,
    const float* __restrict__ scales)
{
    if (blockIdx.x < CONV_BLOCKS) {
        size_t i = ((size_t)blockIdx.x * 256 + threadIdx.x) * 8;
        float4 v0 = *reinterpret_cast<const float4*>(x + i);
        float4 v1 = *reinterpret_cast<const float4*>(x + i + 4);
        __half2 o[4];
        o[0] = __floats2half2_rn(v0.x, v0.y);
        o[1] = __floats2half2_rn(v0.z, v0.w);
        o[2] = __floats2half2_rn(v1.x, v1.y);
        o[3] = __floats2half2_rn(v1.z, v1.w);
        *reinterpret_cast<uint4*>(&g_X[i]) = *reinterpret_cast<const uint4*>(o);
        return;
    }
    int idx = (blockIdx.x - CONV_BLOCKS) * 256 + threadIdx.x;
    if (idx >= DEQ_ELEMS) return;
    int k = idx / NPACK;
    int c = idx - k * NPACK;
    int g = k >> 7;

    unsigned q = (unsigned)qweight[idx];
    unsigned z = (unsigned)qzeros[g * NPACK + c];

    float4 s0 = *reinterpret_cast<const float4*>(scales + (size_t)g * N_DIM + (size_t)c * 8);
    float4 s1 = *reinterpret_cast<const float4*>(scales + (size_t)g * N_DIM + (size_t)c * 8 + 4);
    float sf[8] = {s0.x, s0.y, s0.z, s0.w, s1.x, s1.y, s1.z, s1.w};

    const int shifts[8] = {0, 16, 4, 20, 8, 24, 12, 28};
    __half2 out[4];
#pragma unroll
    for (int j = 0; j < 4; ++j) {
        int i0 = (int)((q >> shifts[2 * j]) & 0xF) - (int)((z >> shifts[2 * j]) & 0xF);
        int i1 = (int)((q >> shifts[2 * j + 1]) & 0xF) - (int)((z >> shifts[2 * j + 1]) & 0xF);
        out[j] = __floats2half2_rn((float)i0 * sf[2 * j], (float)i1 * sf[2 * j + 1]);
    }
    *reinterpret_cast<uint4*>(&g_W[(size_t)k * N_DIM + (size_t)c * 8]) =
        *reinterpret_cast<const uint4*>(out);
}

// ---------------------------------------------------------------------------
// GEMM: CTA tile 128x128, BK=64, 3-stage cp.async, 8 warps (2x4),
// warp tile 64x32. 107.5 KB smem + <=128 regs -> 2 CTAs/SM = 16 warps/SM
// (4 per SMSP) to cover sync/load windows with independent MMA streams.
// ---------------------------------------------------------------------------
constexpr int BM = 128, BN = 128, BK = 64;
constexpr int NK = K_DIM / BK;          // 64
constexpr int A_LD = BK + 8;            // 72 halves
constexpr int B_LD = BN + 8;            // 136 halves
constexpr int A_STAGE = BM * A_LD;      // 9216 halves
constexpr int B_STAGE = BK * B_LD;      // 8704 halves
constexpr int STAGE_H = A_STAGE + B_STAGE;       // 17920 halves
constexpr int NSTAGE = 3;
constexpr int GEMM_SMEM = NSTAGE * STAGE_H * 2;  // 107,520 B
constexpr int NTHREADS = 256;
constexpr int GROUP_M = 8;
constexpr int MT = M_DIM / BM;          // 32
constexpr int NT = N_DIM / BN;          // 86

extern __shared__ __half smem_h[];

__device__ __forceinline__ uint32_t smem_u32(const void* p) {
    uint32_t a;
    asm("{ .reg .u64 t; cvta.to.shared.u64 t, %1; cvt.u32.u64 %0, t; }"
        : "=r"(a) : "l"(p));
    return a;
}
__device__ __forceinline__ void cpa16(uint32_t s, const void* g) {
    asm volatile("cp.async.cg.shared.global [%0], [%1], 16;\n" :: "r"(s), "l"(g));
}
#define CP_COMMIT() asm volatile("cp.async.commit_group;\n" ::: "memory")
#define CP_WAIT(n)  asm volatile("cp.async.wait_group %0;\n" :: "n"(n) : "memory")

__device__ __forceinline__ void ldsm_x4(uint32_t& r0, uint32_t& r1, uint32_t& r2,
                                        uint32_t& r3, uint32_t addr) {
    asm volatile("ldmatrix.sync.aligned.m8n8.x4.shared.b16 {%0,%1,%2,%3}, [%4];"
                 : "=r"(r0), "=r"(r1), "=r"(r2), "=r"(r3) : "r"(addr));
}
__device__ __forceinline__ void ldsm_x4_t(uint32_t& r0, uint32_t& r1, uint32_t& r2,
                                          uint32_t& r3, uint32_t addr) {
    asm volatile("ldmatrix.sync.aligned.m8n8.x4.trans.shared.b16 {%0,%1,%2,%3}, [%4];"
                 : "=r"(r0), "=r"(r1), "=r"(r2), "=r"(r3) : "r"(addr));
}
__device__ __forceinline__ void mma16816(float* c, const uint32_t* a, const uint32_t* b) {
    asm volatile(
        "mma.sync.aligned.m16n8k16.row.col.f32.f16.f16.f32 "
        "{%0,%1,%2,%3}, {%4,%5,%6,%7}, {%8,%9}, {%0,%1,%2,%3};"
        : "+f"(c[0]), "+f"(c[1]), "+f"(c[2]), "+f"(c[3])
        : "r"(a[0]), "r"(a[1]), "r"(a[2]), "r"(a[3]), "r"(b[0]), "r"(b[1]));
}

// stage load (256 threads): A 1024 chunks (4 iters) + B 1024 chunks (4 iters).
__device__ __forceinline__ void load_stage(uint32_t sb, int tid, int m0, int n0, int kt)
{
    uint32_t a_s = sb;
    uint32_t b_s = sb + A_STAGE * 2;
#pragma unroll
    for (int i = 0; i < 4; ++i) {
        int cid = tid + NTHREADS * i;   // 0..1023
        int row = cid >> 3;             // 0..127
        int kc  = cid & 7;              // 0..7
        cpa16(a_s + (row * A_LD + kc * 8) * 2,
              g_X + (size_t)(m0 + row) * K_DIM + kt + kc * 8);
    }
#pragma unroll
    for (int i = 0; i < 4; ++i) {
        int cid = tid + NTHREADS * i;   // 0..1023
        int row = cid >> 4;             // 0..63
        int nc  = cid & 15;             // 0..15
        cpa16(b_s + (row * B_LD + nc * 8) * 2,
              g_W + (size_t)(kt + row) * N_DIM + n0 + nc * 8);
    }
}

__global__ void __launch_bounds__(NTHREADS, 2) gemm_kernel(
    const float* __restrict__ bias,
    float* __restrict__ out)
{
    const int tid  = threadIdx.x;
    const int warp = tid >> 5;
    const int lane = tid & 31;
    const int wm = warp >> 2;           // 0..1 -> 64-row slab
    const int wn = warp & 3;            // 0..3 -> 32-col slab

    int bid = blockIdx.x;
    int grp = bid / (GROUP_M * NT);
    int rem = bid - grp * (GROUP_M * NT);
    int mt  = grp * GROUP_M + rem % GROUP_M;
    int nt  = rem / GROUP_M;
    const int m0 = mt * BM;
    const int n0 = nt * BN;

    const uint32_t sb = smem_u32(smem_h);

    float c[4][4][4];
#pragma unroll
    for (int i = 0; i < 4; ++i)
#pragma unroll
        for (int j = 0; j < 4; ++j)
#pragma unroll
            for (int e = 0; e < 4; ++e) c[i][j][e] = 0.0f;

    // Prologue: stages 0, 1
#pragma unroll
    for (int s = 0; s < NSTAGE - 1; ++s) {
        load_stage(sb + s * STAGE_H * 2, tid, m0, n0, s * BK);
        CP_COMMIT();
    }

    const int a_row = lane & 15;
    const int a_c8  = (lane >> 4) * 8;
    const int b_row = lane & 15;
    const int b_c8  = (lane >> 4) * 8;

    for (int it = 0; it < NK; ++it) {
        CP_WAIT(1);            // stage `it` resident
        __syncthreads();

        int nxt = it + NSTAGE - 1;
        if (nxt < NK)
            load_stage(sb + (nxt % NSTAGE) * STAGE_H * 2, tid, m0, n0, nxt * BK);
        CP_COMMIT();

        const uint32_t a_s = sb + (it % NSTAGE) * STAGE_H * 2;
        const uint32_t b_s = a_s + A_STAGE * 2;

#pragma unroll
        for (int ks = 0; ks < BK / 16; ++ks) {
            uint32_t af[4][4];
#pragma unroll
            for (int mf = 0; mf < 4; ++mf)
                ldsm_x4(af[mf][0], af[mf][1], af[mf][2], af[mf][3],
                        a_s + ((wm * 64 + mf * 16 + a_row) * A_LD + ks * 16 + a_c8) * 2);
            uint32_t bf[2][4];
#pragma unroll
            for (int nb = 0; nb < 2; ++nb)
                ldsm_x4_t(bf[nb][0], bf[nb][1], bf[nb][2], bf[nb][3],
                          b_s + ((ks * 16 + b_row) * B_LD + wn * 32 + nb * 16 + b_c8) * 2);
#pragma unroll
            for (int mf = 0; mf < 4; ++mf) {
#pragma unroll
                for (int nf = 0; nf < 4; ++nf) {
                    const uint32_t* bp = &bf[nf >> 1][(nf & 1) * 2];
                    mma16816(c[mf][nf], af[mf], bp);
                }
            }
        }
    }

    // -------- epilogue: fp16 round + fp16 bias, f32 stores ----------
    const int qr = lane >> 2;            // 0..7
    const int qc = (lane & 3) * 2;       // 0,2,4,6
#pragma unroll
    for (int nf = 0; nf < 4; ++nf) {
        int col = n0 + wn * 32 + nf * 8 + qc;
        float2 bv = *reinterpret_cast<const float2*>(bias + col);
        __half bh0 = __float2half(bv.x), bh1 = __float2half(bv.y);
#pragma unroll
        for (int mf = 0; mf < 4; ++mf) {
            int row = m0 + wm * 64 + mf * 16 + qr;
            float2 o0, o1;
            o0.x = __half2float(__hadd(__float2half(c[mf][nf][0]), bh0));
            o0.y = __half2float(__hadd(__float2half(c[mf][nf][1]), bh1));
            o1.x = __half2float(__hadd(__float2half(c[mf][nf][2]), bh0));
            o1.y = __half2float(__hadd(__float2half(c[mf][nf][3]), bh1));
            *reinterpret_cast<float2*>(&out[(size_t)row * N_DIM + col]) = o0;
            *reinterpret_cast<float2*>(&out[(size_t)(row + 8) * N_DIM + col]) = o1;
        }
    }
}

// ---------------------------------------------------------------------------
extern "C" void kernel_launch(void* const* d_in, const int* in_sizes, int n_in,
                              void* d_out, int out_size)
{
    const float* x      = (const float*)d_in[0];
    const int*   qw     = (const int*)d_in[1];
    const int*   qz     = (const int*)d_in[2];
    const float* scales = (const float*)d_in[3];
    const float* bias   = (const float*)d_in[4];
    float*       out    = (float*)d_out;

    cudaFuncSetAttribute(gemm_kernel, cudaFuncAttributeMaxDynamicSharedMemorySize,
                         GEMM_SMEM);

    prep_kernel<<<CONV_BLOCKS + DEQ_BLOCKS, 256>>>(x, qw, qz, scales);
    gemm_kernel<<<MT * NT, NTHREADS, GEMM_SMEM>>>(bias, out);
}

// round 12
// speedup vs baseline: 1.2560x; 1.1588x over previous
#include <cuda_runtime.h>
#include <cuda_fp16.h>
#include <cstdint>

#define M_DIM 4096
#define K_DIM 4096
#define N_DIM 11008
#define NPACK (N_DIM / 8)   // 1376
#define GROUP 128

// Static scratch: W [K, N] fp16 (90.2 MB) + X [M, K] fp16 (32 MB).
__device__ __half g_W[(size_t)K_DIM * N_DIM];
__device__ __half g_X[(size_t)M_DIM * K_DIM];

// ---------------------------------------------------------------------------
// Fused prep: block.x < CONV_BLOCKS -> convert x f32->fp16; else AWQ dequant.
// ---------------------------------------------------------------------------
constexpr int CONV_BLOCKS = (M_DIM * K_DIM / 8) / 256;          // 8192
constexpr int DEQ_ELEMS   = K_DIM * NPACK;                      // 5,636,096
constexpr int DEQ_BLOCKS  = (DEQ_ELEMS + 255) / 256;            // 22016

__global__ void __launch_bounds__(256) prep_kernel(
    const float* __restrict__ x,
    const int* __restrict__ qweight,
    const int* __restrict__ qzeros,
    const float* __restrict__ scales)
{
    if (blockIdx.x < CONV_BLOCKS) {
        size_t i = ((size_t)blockIdx.x * 256 + threadIdx.x) * 8;
        float4 v0 = *reinterpret_cast<const float4*>(x + i);
        float4 v1 = *reinterpret_cast<const float4*>(x + i + 4);
        __half2 o[4];
        o[0] = __floats2half2_rn(v0.x, v0.y);
        o[1] = __floats2half2_rn(v0.z, v0.w);
        o[2] = __floats2half2_rn(v1.x, v1.y);
        o[3] = __floats2half2_rn(v1.z, v1.w);
        *reinterpret_cast<uint4*>(&g_X[i]) = *reinterpret_cast<const uint4*>(o);
        return;
    }
    int idx = (blockIdx.x - CONV_BLOCKS) * 256 + threadIdx.x;
    if (idx >= DEQ_ELEMS) return;
    int k = idx / NPACK;
    int c = idx - k * NPACK;
    int g = k >> 7;

    unsigned q = (unsigned)qweight[idx];
    unsigned z = (unsigned)qzeros[g * NPACK + c];

    float4 s0 = *reinterpret_cast<const float4*>(scales + (size_t)g * N_DIM + (size_t)c * 8);
    float4 s1 = *reinterpret_cast<const float4*>(scales + (size_t)g * N_DIM + (size_t)c * 8 + 4);
    float sf[8] = {s0.x, s0.y, s0.z, s0.w, s1.x, s1.y, s1.z, s1.w};

    const int shifts[8] = {0, 16, 4, 20, 8, 24, 12, 28};
    __half2 out[4];
#pragma unroll
    for (int j = 0; j < 4; ++j) {
        int i0 = (int)((q >> shifts[2 * j]) & 0xF) - (int)((z >> shifts[2 * j]) & 0xF);
        int i1 = (int)((q >> shifts[2 * j + 1]) & 0xF) - (int)((z >> shifts[2 * j + 1]) & 0xF);
        out[j] = __floats2half2_rn((float)i0 * sf[2 * j], (float)i1 * sf[2 * j + 1]);
    }
    *reinterpret_cast<uint4*>(&g_W[(size_t)k * N_DIM + (size_t)c * 8]) =
        *reinterpret_cast<const uint4*>(out);
}

// ---------------------------------------------------------------------------
// GEMM: CTA tile 128x128, BK=64, 3-stage cp.async, 4 warps (2x2),
// warp tile 64x64, 2 CTAs/SM. cp.async bursts interleaved INTO the MMA
// stream (after ks=0 / ks=1) so the LSU drain overlaps HMMA issue.
// ---------------------------------------------------------------------------
constexpr int BM = 128, BN = 128, BK = 64;
constexpr int NK = K_DIM / BK;          // 64
constexpr int A_LD = BK + 8;            // 72 halves
constexpr int B_LD = BN + 8;            // 136 halves
constexpr int A_STAGE = BM * A_LD;      // 9216 halves
constexpr int B_STAGE = BK * B_LD;      // 8704 halves
constexpr int STAGE_H = A_STAGE + B_STAGE;       // 17920 halves
constexpr int NSTAGE = 3;
constexpr int GEMM_SMEM = NSTAGE * STAGE_H * 2;  // 107,520 B
constexpr int NTHREADS = 128;
constexpr int GROUP_M = 8;
constexpr int MT = M_DIM / BM;          // 32
constexpr int NT = N_DIM / BN;          // 86

extern __shared__ __half smem_h[];

__device__ __forceinline__ uint32_t smem_u32(const void* p) {
    uint32_t a;
    asm("{ .reg .u64 t; cvta.to.shared.u64 t, %1; cvt.u32.u64 %0, t; }"
        : "=r"(a) : "l"(p));
    return a;
}
__device__ __forceinline__ void cpa16(uint32_t s, const void* g) {
    asm volatile("cp.async.cg.shared.global [%0], [%1], 16;\n" :: "r"(s), "l"(g));
}
#define CP_COMMIT() asm volatile("cp.async.commit_group;\n" ::: "memory")
#define CP_WAIT(n)  asm volatile("cp.async.wait_group %0;\n" :: "n"(n) : "memory")

__device__ __forceinline__ void ldsm_x4(uint32_t& r0, uint32_t& r1, uint32_t& r2,
                                        uint32_t& r3, uint32_t addr) {
    asm volatile("ldmatrix.sync.aligned.m8n8.x4.shared.b16 {%0,%1,%2,%3}, [%4];"
                 : "=r"(r0), "=r"(r1), "=r"(r2), "=r"(r3) : "r"(addr));
}
__device__ __forceinline__ void ldsm_x4_t(uint32_t& r0, uint32_t& r1, uint32_t& r2,
                                          uint32_t& r3, uint32_t addr) {
    asm volatile("ldmatrix.sync.aligned.m8n8.x4.trans.shared.b16 {%0,%1,%2,%3}, [%4];"
                 : "=r"(r0), "=r"(r1), "=r"(r2), "=r"(r3) : "r"(addr));
}
__device__ __forceinline__ void mma16816(float* c, const uint32_t* a, const uint32_t* b) {
    asm volatile(
        "mma.sync.aligned.m16n8k16.row.col.f32.f16.f16.f32 "
        "{%0,%1,%2,%3}, {%4,%5,%6,%7}, {%8,%9}, {%0,%1,%2,%3};"
        : "+f"(c[0]), "+f"(c[1]), "+f"(c[2]), "+f"(c[3])
        : "r"(a[0]), "r"(a[1]), "r"(a[2]), "r"(a[3]), "r"(b[0]), "r"(b[1]));
}

// Split stage loaders (128 threads): A 1024 chunks, B 1024 chunks.
__device__ __forceinline__ void load_stage_A(uint32_t a_s, int tid, int m0, int kt)
{
#pragma unroll
    for (int i = 0; i < 8; ++i) {
        int cid = tid + NTHREADS * i;
        int row = cid >> 3;             // 0..127
        int kc  = cid & 7;              // 0..7
        cpa16(a_s + (row * A_LD + kc * 8) * 2,
              g_X + (size_t)(m0 + row) * K_DIM + kt + kc * 8);
    }
}
__device__ __forceinline__ void load_stage_B(uint32_t b_s, int tid, int n0, int kt)
{
#pragma unroll
    for (int i = 0; i < 8; ++i) {
        int cid = tid + NTHREADS * i;
        int row = cid >> 4;             // 0..63
        int nc  = cid & 15;             // 0..15
        cpa16(b_s + (row * B_LD + nc * 8) * 2,
              g_W + (size_t)(kt + row) * N_DIM + n0 + nc * 8);
    }
}

// one ks step: ldmatrix fragments + 32 MMAs
#define KS_STEP(ks) do {                                                     \
    uint32_t af[4][4], bf[4][4];                                             \
    _Pragma("unroll")                                                        \
    for (int mf = 0; mf < 4; ++mf)                                           \
        ldsm_x4(af[mf][0], af[mf][1], af[mf][2], af[mf][3],                  \
                a_s + ((wm * 64 + mf * 16 + a_row) * A_LD + (ks) * 16 + a_c8) * 2); \
    _Pragma("unroll")                                                        \
    for (int nb = 0; nb < 4; ++nb)                                           \
        ldsm_x4_t(bf[nb][0], bf[nb][1], bf[nb][2], bf[nb][3],                \
                  b_s + (((ks) * 16 + b_row) * B_LD + wn * 64 + nb * 16 + b_c8) * 2); \
    _Pragma("unroll")                                                        \
    for (int mf = 0; mf < 4; ++mf) {                                         \
        _Pragma("unroll")                                                    \
        for (int nf = 0; nf < 8; ++nf) {                                     \
            const uint32_t* bp = &bf[nf >> 1][(nf & 1) * 2];                 \
            mma16816(c[mf][nf], af[mf], bp);                                 \
        }                                                                    \
    }                                                                        \
} while (0)

__global__ void __launch_bounds__(NTHREADS, 2) gemm_kernel(
    const float* __restrict__ bias,
    float* __restrict__ out)
{
    const int tid  = threadIdx.x;
    const int warp = tid >> 5;
    const int lane = tid & 31;
    const int wm = warp >> 1;           // 0..1 -> 64-row slab
    const int wn = warp & 1;            // 0..1 -> 64-col slab

    int bid = blockIdx.x;
    int grp = bid / (GROUP_M * NT);
    int rem = bid - grp * (GROUP_M * NT);
    int mt  = grp * GROUP_M + rem % GROUP_M;
    int nt  = rem / GROUP_M;
    const int m0 = mt * BM;
    const int n0 = nt * BN;

    const uint32_t sb = smem_u32(smem_h);

    float c[4][8][4];
#pragma unroll
    for (int i = 0; i < 4; ++i)
#pragma unroll
        for (int j = 0; j < 8; ++j)
#pragma unroll
            for (int e = 0; e < 4; ++e) c[i][j][e] = 0.0f;

    // Prologue: stages 0, 1
#pragma unroll
    for (int s = 0; s < NSTAGE - 1; ++s) {
        load_stage_A(sb + s * STAGE_H * 2, tid, m0, s * BK);
        load_stage_B(sb + s * STAGE_H * 2 + A_STAGE * 2, tid, n0, s * BK);
        CP_COMMIT();
    }

    const int a_row = lane & 15;
    const int a_c8  = (lane >> 4) * 8;
    const int b_row = lane & 15;
    const int b_c8  = (lane >> 4) * 8;

    for (int it = 0; it < NK; ++it) {
        CP_WAIT(1);            // stage `it` resident
        __syncthreads();

        const uint32_t a_s = sb + (it % NSTAGE) * STAGE_H * 2;
        const uint32_t b_s = a_s + A_STAGE * 2;

        const int nxt = it + NSTAGE - 1;
        const bool have_next = nxt < NK;
        const uint32_t nsb = sb + (nxt % NSTAGE) * STAGE_H * 2;

        // ks=0: MMAs first — tensor pipe starts immediately after barrier
        KS_STEP(0);
        // A-half of next-stage loads drains under ks=1..3 MMA issue
        if (have_next) load_stage_A(nsb, tid, m0, nxt * BK);
        KS_STEP(1);
        if (have_next) load_stage_B(nsb + A_STAGE * 2, tid, n0, nxt * BK);
        KS_STEP(2);
        KS_STEP(3);

        CP_COMMIT();           // exactly one group per iteration
    }

    // -------- epilogue: fp16 round + fp16 bias, f32 stores ----------
    const int qr = lane >> 2;            // 0..7
    const int qc = (lane & 3) * 2;       // 0,2,4,6
#pragma unroll
    for (int nf = 0; nf < 8; ++nf) {
        int col = n0 + wn * 64 + nf * 8 + qc;
        float2 bv = *reinterpret_cast<const float2*>(bias + col);
        __half bh0 = __float2half(bv.x), bh1 = __float2half(bv.y);
#pragma unroll
        for (int mf = 0; mf < 4; ++mf) {
            int row = m0 + wm * 64 + mf * 16 + qr;
            float2 o0, o1;
            o0.x = __half2float(__hadd(__float2half(c[mf][nf][0]), bh0));
            o0.y = __half2float(__hadd(__float2half(c[mf][nf][1]), bh1));
            o1.x = __half2float(__hadd(__float2half(c[mf][nf][2]), bh0));
            o1.y = __half2float(__hadd(__float2half(c[mf][nf][3]), bh1));
            *reinterpret_cast<float2*>(&out[(size_t)row * N_DIM + col]) = o0;
            *reinterpret_cast<float2*>(&out[(size_t)(row + 8) * N_DIM + col]) = o1;
        }
    }
}

// ---------------------------------------------------------------------------
extern "C" void kernel_launch(void* const* d_in, const int* in_sizes, int n_in,
                              void* d_out, int out_size)
{
    const float* x      = (const float*)d_in[0];
    const int*   qw     = (const int*)d_in[1];
    const int*   qz     = (const int*)d_in[2];
    const float* scales = (const float*)d_in[3];
    const float* bias   = (const float*)d_in[4];
    float*       out    = (float*)d_out;

    cudaFuncSetAttribute(gemm_kernel, cudaFuncAttributeMaxDynamicSharedMemorySize,
                         GEMM_SMEM);

    prep_kernel<<<CONV_BLOCKS + DEQ_BLOCKS, 256>>>(x, qw, qz, scales);
    gemm_kernel<<<MT * NT, NTHREADS, GEMM_SMEM>>>(bias, out);
}

// round 14
// speedup vs baseline: 1.3189x; 1.0500x over previous
#include <cuda_runtime.h>
#include <cuda_fp16.h>
#include <cstdint>

#define M_DIM 4096
#define K_DIM 4096
#define N_DIM 11008
#define NPACK (N_DIM / 8)   // 1376
#define GROUP 128

// Static scratch: W [K, N] fp16 (90.2 MB) + X [M, K] fp16 (32 MB).
__device__ __half g_W[(size_t)K_DIM * N_DIM];
__device__ __half g_X[(size_t)M_DIM * K_DIM];

// ---------------------------------------------------------------------------
// Fused prep: block.x < CONV_BLOCKS -> convert x f32->fp16; else AWQ dequant.
// ---------------------------------------------------------------------------
constexpr int CONV_BLOCKS = (M_DIM * K_DIM / 8) / 256;          // 8192
constexpr int DEQ_ELEMS   = K_DIM * NPACK;                      // 5,636,096
constexpr int DEQ_BLOCKS  = (DEQ_ELEMS + 255) / 256;            // 22016

__global__ void __launch_bounds__(256) prep_kernel(
    const float* __restrict__ x,
    const int* __restrict__ qweight,
    const int* __restrict__ qzeros,
    const float* __restrict__ scales)
{
    if (blockIdx.x < CONV_BLOCKS) {
        size_t i = ((size_t)blockIdx.x * 256 + threadIdx.x) * 8;
        float4 v0 = *reinterpret_cast<const float4*>(x + i);
        float4 v1 = *reinterpret_cast<const float4*>(x + i + 4);
        __half2 o[4];
        o[0] = __floats2half2_rn(v0.x, v0.y);
        o[1] = __floats2half2_rn(v0.z, v0.w);
        o[2] = __floats2half2_rn(v1.x, v1.y);
        o[3] = __floats2half2_rn(v1.z, v1.w);
        *reinterpret_cast<uint4*>(&g_X[i]) = *reinterpret_cast<const uint4*>(o);
        return;
    }
    int idx = (blockIdx.x - CONV_BLOCKS) * 256 + threadIdx.x;
    if (idx >= DEQ_ELEMS) return;
    int k = idx / NPACK;
    int c = idx - k * NPACK;
    int g = k >> 7;

    unsigned q = (unsigned)qweight[idx];
    unsigned z = (unsigned)qzeros[g * NPACK + c];

    float4 s0 = *reinterpret_cast<const float4*>(scales + (size_t)g * N_DIM + (size_t)c * 8);
    float4 s1 = *reinterpret_cast<const float4*>(scales + (size_t)g * N_DIM + (size_t)c * 8 + 4);
    float sf[8] = {s0.x, s0.y, s0.z, s0.w, s1.x, s1.y, s1.z, s1.w};

    const int shifts[8] = {0, 16, 4, 20, 8, 24, 12, 28};
    __half2 out[4];
#pragma unroll
    for (int j = 0; j < 4; ++j) {
        int i0 = (int)((q >> shifts[2 * j]) & 0xF) - (int)((z >> shifts[2 * j]) & 0xF);
        int i1 = (int)((q >> shifts[2 * j + 1]) & 0xF) - (int)((z >> shifts[2 * j + 1]) & 0xF);
        out[j] = __floats2half2_rn((float)i0 * sf[2 * j], (float)i1 * sf[2 * j + 1]);
    }
    *reinterpret_cast<uint4*>(&g_W[(size_t)k * N_DIM + (size_t)c * 8]) =
        *reinterpret_cast<const uint4*>(out);
}

// ---------------------------------------------------------------------------
// GEMM: CTA tile 128x128, BK=64, 3-stage pipeline with mbarrier full/empty
// pairs (no CTA-wide barrier in the mainloop). 4 warps (2x2), warp tile
// 64x64, 2 CTAs/SM. Loads interleaved into the MMA stream.
// Fixes vs r13: cp.async.mbarrier.arrive.NOINC; producer skips the empty-
// wait ONLY for slot 2's first fill (it==0) and uses parity 0,0,0,1,1,1,...
// ---------------------------------------------------------------------------
constexpr int BM = 128, BN = 128, BK = 64;
constexpr int NK = K_DIM / BK;          // 64
constexpr int A_LD = BK + 8;            // 72 halves
constexpr int B_LD = BN + 8;            // 136 halves
constexpr int A_STAGE = BM * A_LD;      // 9216 halves
constexpr int B_STAGE = BK * B_LD;      // 8704 halves
constexpr int STAGE_H = A_STAGE + B_STAGE;       // 17920 halves
constexpr int NSTAGE = 3;
constexpr int STAGE0_OFF = 128;          // barriers live below
constexpr int GEMM_SMEM = STAGE0_OFF + NSTAGE * STAGE_H * 2;  // 107,648 B
constexpr int NTHREADS = 128;
constexpr int GROUP_M = 8;
constexpr int MT = M_DIM / BM;          // 32
constexpr int NT = N_DIM / BN;          // 86

extern __shared__ __half smem_h[];

__device__ __forceinline__ uint32_t smem_u32(const void* p) {
    uint32_t a;
    asm("{ .reg .u64 t; cvta.to.shared.u64 t, %1; cvt.u32.u64 %0, t; }"
        : "=r"(a) : "l"(p));
    return a;
}
__device__ __forceinline__ void cpa16(uint32_t s, const void* g) {
    asm volatile("cp.async.cg.shared.global [%0], [%1], 16;\n" :: "r"(s), "l"(g));
}
// .noinc: the async completion consumes one of the barrier's expected
// arrivals (without .noinc the pend-count is bumped at issue -> net zero).
#define CPA_MBAR_ARRIVE(mb) \
    asm volatile("cp.async.mbarrier.arrive.noinc.shared.b64 [%0];" :: "r"(mb) : "memory")
#define MBAR_INIT(a, c) \
    asm volatile("mbarrier.init.shared.b64 [%0], %1;" :: "r"(a), "r"(c) : "memory")
#define MBAR_ARRIVE(a) \
    asm volatile("mbarrier.arrive.shared.b64 _, [%0];" :: "r"(a) : "memory")
// returns when barrier's current phase != ph (i.e., phase `ph` completed)
#define MBAR_WAIT(a, ph) do { \
    uint32_t _m = (a), _p = (ph), _d; \
    asm volatile("{\n\t.reg .pred p;\n\t" \
        "mbarrier.try_wait.parity.acquire.cta.shared::cta.b64 p, [%1], %2;\n\t" \
        "selp.b32 %0, 1, 0, p;\n\t}" : "=r"(_d) : "r"(_m), "r"(_p) : "memory"); \
    if (!_d) { \
        asm volatile("{\n\t.reg .pred P1;\n\tW%=:\n\t" \
            "mbarrier.try_wait.parity.acquire.cta.shared::cta.b64 P1, [%0], %1, 0x989680;\n\t" \
            "@P1 bra.uni D%=;\n\tbra.uni W%=;\n\tD%=:\n\t}" \
            :: "r"(_m), "r"(_p) : "memory"); \
    } \
} while (0)

__device__ __forceinline__ void ldsm_x4(uint32_t& r0, uint32_t& r1, uint32_t& r2,
                                        uint32_t& r3, uint32_t addr) {
    asm volatile("ldmatrix.sync.aligned.m8n8.x4.shared.b16 {%0,%1,%2,%3}, [%4];"
                 : "=r"(r0), "=r"(r1), "=r"(r2), "=r"(r3) : "r"(addr));
}
__device__ __forceinline__ void ldsm_x4_t(uint32_t& r0, uint32_t& r1, uint32_t& r2,
                                          uint32_t& r3, uint32_t addr) {
    asm volatile("ldmatrix.sync.aligned.m8n8.x4.trans.shared.b16 {%0,%1,%2,%3}, [%4];"
                 : "=r"(r0), "=r"(r1), "=r"(r2), "=r"(r3) : "r"(addr));
}
__device__ __forceinline__ void mma16816(float* c, const uint32_t* a, const uint32_t* b) {
    asm volatile(
        "mma.sync.aligned.m16n8k16.row.col.f32.f16.f16.f32 "
        "{%0,%1,%2,%3}, {%4,%5,%6,%7}, {%8,%9}, {%0,%1,%2,%3};"
        : "+f"(c[0]), "+f"(c[1]), "+f"(c[2]), "+f"(c[3])
        : "r"(a[0]), "r"(a[1]), "r"(a[2]), "r"(a[3]), "r"(b[0]), "r"(b[1]));
}

// Split stage loaders (128 threads): A 1024 chunks, B 1024 chunks.
__device__ __forceinline__ void load_stage_A(uint32_t a_s, int tid, int m0, int kt)
{
#pragma unroll
    for (int i = 0; i < 8; ++i) {
        int cid = tid + NTHREADS * i;
        int row = cid >> 3;             // 0..127
        int kc  = cid & 7;              // 0..7
        cpa16(a_s + (row * A_LD + kc * 8) * 2,
              g_X + (size_t)(m0 + row) * K_DIM + kt + kc * 8);
    }
}
__device__ __forceinline__ void load_stage_B(uint32_t b_s, int tid, int n0, int kt)
{
#pragma unroll
    for (int i = 0; i < 8; ++i) {
        int cid = tid + NTHREADS * i;
        int row = cid >> 4;             // 0..63
        int nc  = cid & 15;             // 0..15
        cpa16(b_s + (row * B_LD + nc * 8) * 2,
              g_W + (size_t)(kt + row) * N_DIM + n0 + nc * 8);
    }
}

// one ks step: ldmatrix fragments + 32 MMAs
#define KS_STEP(ks) do {                                                     \
    uint32_t af[4][4], bf[4][4];                                             \
    _Pragma("unroll")                                                        \
    for (int mf = 0; mf < 4; ++mf)                                           \
        ldsm_x4(af[mf][0], af[mf][1], af[mf][2], af[mf][3],                  \
                a_s + ((wm * 64 + mf * 16 + a_row) * A_LD + (ks) * 16 + a_c8) * 2); \
    _Pragma("unroll")                                                        \
    for (int nb = 0; nb < 4; ++nb)                                           \
        ldsm_x4_t(bf[nb][0], bf[nb][1], bf[nb][2], bf[nb][3],                \
                  b_s + (((ks) * 16 + b_row) * B_LD + wn * 64 + nb * 16 + b_c8) * 2); \
    _Pragma("unroll")                                                        \
    for (int mf = 0; mf < 4; ++mf) {                                         \
        _Pragma("unroll")                                                    \
        for (int nf = 0; nf < 8; ++nf) {                                     \
            const uint32_t* bp = &bf[nf >> 1][(nf & 1) * 2];                 \
            mma16816(c[mf][nf], af[mf], bp);                                 \
        }                                                                    \
    }                                                                        \
} while (0)

__global__ void __launch_bounds__(NTHREADS, 2) gemm_kernel(
    const float* __restrict__ bias,
    float* __restrict__ out)
{
    const int tid  = threadIdx.x;
    const int warp = tid >> 5;
    const int lane = tid & 31;
    const int wm = warp >> 1;           // 0..1 -> 64-row slab
    const int wn = warp & 1;            // 0..1 -> 64-col slab

    int bid = blockIdx.x;
    int grp = bid / (GROUP_M * NT);
    int rem = bid - grp * (GROUP_M * NT);
    int mt  = grp * GROUP_M + rem % GROUP_M;
    int nt  = rem / GROUP_M;
    const int m0 = mt * BM;
    const int n0 = nt * BN;

    const uint32_t sb = smem_u32(smem_h);
    // barriers: full[s] = sb + s*16, empty[s] = sb + s*16 + 8
    const uint32_t stg0 = sb + STAGE0_OFF;

    if (tid == 0) {
#pragma unroll
        for (int s = 0; s < NSTAGE; ++s) {
            MBAR_INIT(sb + s * 16,     NTHREADS);   // full
            MBAR_INIT(sb + s * 16 + 8, NTHREADS);   // empty
        }
    }
    __syncthreads();   // barriers visible before any arrive/wait

    float c[4][8][4];
#pragma unroll
    for (int i = 0; i < 4; ++i)
#pragma unroll
        for (int j = 0; j < 8; ++j)
#pragma unroll
            for (int e = 0; e < 4; ++e) c[i][j][e] = 0.0f;

    // Prologue: produce stages 0, 1 (fresh slots -> no wait)
    load_stage_A(stg0, tid, m0, 0);
    load_stage_B(stg0 + A_STAGE * 2, tid, n0, 0);
    CPA_MBAR_ARRIVE(sb + 0 * 16);
    load_stage_A(stg0 + STAGE_H * 2, tid, m0, BK);
    load_stage_B(stg0 + STAGE_H * 2 + A_STAGE * 2, tid, n0, BK);
    CPA_MBAR_ARRIVE(sb + 1 * 16);

    const int a_row = lane & 15;
    const int a_c8  = (lane >> 4) * 8;
    const int b_row = lane & 15;
    const int b_c8  = (lane >> 4) * 8;

    // consumer cursor: stage it lives in slot it%3; fill round (it/3)&1
    int slotc = 0, phasec = 0;
    // producer cursor: stage it+2 -> slot (it+2)%3. First fill (it==0,
    // slot 2) needs no wait. Required wait parities from it=1:
    // 0,0,0,1,1,1,... -> start pparity=1 and flip on wrap (wrap happens
    // between it=0 and it=1, making it=1..3 parity 0).
    int slotp = 2, phasep = 1;

    for (int it = 0; it < NK; ++it) {
        MBAR_WAIT(sb + slotc * 16, phasec);          // stage `it` full
        const uint32_t a_s = stg0 + slotc * STAGE_H * 2;
        const uint32_t b_s = a_s + A_STAGE * 2;

        const bool have_next = (it + 2) < NK;
        const uint32_t psb = stg0 + slotp * STAGE_H * 2;

        KS_STEP(0);
        if (have_next) {
            if (it > 0)                              // slot2 first fill: fresh
                MBAR_WAIT(sb + slotp * 16 + 8, phasep);
            load_stage_A(psb, tid, m0, (it + 2) * BK);
        }
        KS_STEP(1);
        if (have_next) {
            load_stage_B(psb + A_STAGE * 2, tid, n0, (it + 2) * BK);
            CPA_MBAR_ARRIVE(sb + slotp * 16);        // full when loads land
        }
        KS_STEP(2);
        KS_STEP(3);

        MBAR_ARRIVE(sb + slotc * 16 + 8);            // done reading stage `it`

        if (++slotc == NSTAGE) { slotc = 0; phasec ^= 1; }
        if (++slotp == NSTAGE) { slotp = 0; phasep ^= 1; }
    }

    // -------- epilogue: fp16 round + fp16 bias, f32 stores ----------
    const int qr = lane >> 2;            // 0..7
    const int qc = (lane & 3) * 2;       // 0,2,4,6
#pragma unroll
    for (int nf = 0; nf < 8; ++nf) {
        int col = n0 + wn * 64 + nf * 8 + qc;
        float2 bv = *reinterpret_cast<const float2*>(bias + col);
        __half bh0 = __float2half(bv.x), bh1 = __float2half(bv.y);
#pragma unroll
        for (int mf = 0; mf < 4; ++mf) {
            int row = m0 + wm * 64 + mf * 16 + qr;
            float2 o0, o1;
            o0.x = __half2float(__hadd(__float2half(c[mf][nf][0]), bh0));
            o0.y = __half2float(__hadd(__float2half(c[mf][nf][1]), bh1));
            o1.x = __half2float(__hadd(__float2half(c[mf][nf][2]), bh0));
            o1.y = __half2float(__hadd(__float2half(c[mf][nf][3]), bh1));
            *reinterpret_cast<float2*>(&out[(size_t)row * N_DIM + col]) = o0;
            *reinterpret_cast<float2*>(&out[(size_t)(row + 8) * N_DIM + col]) = o1;
        }
    }
}

// ---------------------------------------------------------------------------
extern "C" void kernel_launch(void* const* d_in, const int* in_sizes, int n_in,
                              void* d_out, int out_size)
{
    const float* x      = (const float*)d_in[0];
    const int*   qw     = (const int*)d_in[1];
    const int*   qz     = (const int*)d_in[2];
    const float* scales = (const float*)d_in[3];
    const float* bias   = (const float*)d_in[4];
    float*       out    = (float*)d_out;

    cudaFuncSetAttribute(gemm_kernel, cudaFuncAttributeMaxDynamicSharedMemorySize,
                         GEMM_SMEM);

    prep_kernel<<<CONV_BLOCKS + DEQ_BLOCKS, 256>>>(x, qw, qz, scales);
    gemm_kernel<<<MT * NT, NTHREADS, GEMM_SMEM>>>(bias, out);
}